// round 4
// baseline (speedup 1.0000x reference)
#include <cuda_runtime.h>

#define NBOX 10647
#define NCLS 80
#define MAXDET 300
#define SCORE_THR 0.3f
#define IOU_THR 0.45f
#define INPUT_SZ 416.0
#define MAXPER 1024            // per-class bucket capacity (expected ~93)
#define MAXPICK (NCLS * MAXDET)  // 24000: hard bound on stored picks

// Per-class buckets written by decode, read by class NMS.
__device__ float4             g_bbox[NCLS * MAXPER];
__device__ unsigned long long g_bkey[NCLS * MAXPER];
__device__ int                g_cnt[NCLS];

// Compact pick list written by class NMS, read by select.
__device__ unsigned long long g_pkey[MAXPICK];
__device__ int                g_pcls[MAXPICK];
__device__ int                g_ptotal;

// ---------------------------------------------------------------------------
// Init: zero output rows and counters (graph replays reuse state).
// ---------------------------------------------------------------------------
__global__ void init_kernel(float* __restrict__ out) {
    int t = blockIdx.x * blockDim.x + threadIdx.x;
    if (t < MAXDET * 6) out[t] = 0.0f;
    if (t < NCLS) g_cnt[t] = 0;
    if (t == NCLS) g_ptotal = 0;
}

// ---------------------------------------------------------------------------
// Decode: one warp per box. Lanes cooperatively argmax the 80 class probs
// (tie -> lowest class index, matching jnp.argmax), lane 0 does box math and
// scatters surviving boxes into per-class buckets.
// ---------------------------------------------------------------------------
__global__ void decode_kernel(const float* __restrict__ pred,
                              const int* __restrict__ p_oh,
                              const int* __restrict__ p_ow) {
    int gt   = blockIdx.x * blockDim.x + threadIdx.x;
    int box  = gt >> 5;
    int lane = gt & 31;
    if (box >= NBOX) return;

    const float* p = pred + box * 85;

    float best = -1.0f;
    int bestc = 0;
    for (int c = lane; c < NCLS; c += 32) {
        float v = p[5 + c];
        if (v > best) { best = v; bestc = c; }
    }
    for (int off = 16; off; off >>= 1) {
        float v2 = __shfl_xor_sync(0xffffffffu, best, off);
        int   c2 = __shfl_xor_sync(0xffffffffu, bestc, off);
        if (v2 > best || (v2 == best && c2 < bestc)) { best = v2; bestc = c2; }
    }
    if (lane) return;

    int oh = p_oh[0];
    int ow = p_ow[0];
    double rw = INPUT_SZ / (double)ow;
    double rh = INPUT_SZ / (double)oh;
    double rr = rw < rh ? rw : rh;
    float dw = (float)((INPUT_SZ - rr * (double)ow) * 0.5);
    float dh = (float)((INPUT_SZ - rr * (double)oh) * 0.5);
    float r  = (float)rr;

    float cx = p[0], cy = p[1], w = p[2], h = p[3], conf = p[4];
    float x1 = (cx - w * 0.5f - dw) / r;
    float y1 = (cy - h * 0.5f - dh) / r;
    float x2 = (cx + w * 0.5f - dw) / r;
    float y2 = (cy + h * 0.5f - dh) / r;
    x1 = fmaxf(x1, 0.0f);
    y1 = fmaxf(y1, 0.0f);
    x2 = fminf(x2, (float)(ow - 1));
    y2 = fminf(y2, (float)(oh - 1));
    if (x1 > x2 || y1 > y2) { x1 = y1 = x2 = y2 = 0.0f; }

    float area  = (x2 - x1) * (y2 - y1);
    float score = conf * best;
    if (!(area > 0.0f && score > SCORE_THR)) return;

    int slot = atomicAdd(&g_cnt[bestc], 1);
    if (slot < MAXPER) {
        g_bbox[bestc * MAXPER + slot] = make_float4(x1, y1, x2, y2);
        // key: score (desc) > orig index (asc, via NBOX-box) > slot (10 bits,
        // needed to recover the box; (NBOX-box) already makes keys unique).
        g_bkey[bestc * MAXPER + slot] =
            ((unsigned long long)__float_as_uint(score) << 32) |
            ((unsigned long long)(NBOX - box) << 10) |
            (unsigned long long)(slot & (MAXPER - 1));
    }
}

// ---------------------------------------------------------------------------
// Per-class NMS: one warp per class. Bitonic-sort the bucket's keys desc,
// then sorted-scan: keep a candidate iff no already-kept box of this class
// overlaps with IoU > 0.45. Picks (<=300/class) go to a compact global list.
// Greedy-NMS == sorted-scan because suppression is class-local and picks
// within a class occur in descending key order.
// ---------------------------------------------------------------------------
__global__ __launch_bounds__(32, 1) void class_nms_kernel() {
    __shared__ unsigned long long skey[MAXPER];    // 8 KB
    __shared__ float4             sbox[MAXPER];    // 16 KB
    __shared__ unsigned short     skept[MAXPER];   // 2 KB  (slots of kept boxes)
    __shared__ unsigned long long spick[MAXDET];   // 2.4 KB

    int c    = blockIdx.x;
    int lane = threadIdx.x;

    int n = g_cnt[c];
    if (n > MAXPER) n = MAXPER;
    if (n == 0) return;

    int NP = 32;
    while (NP < n) NP <<= 1;

    for (int j = lane; j < NP; j += 32)
        skey[j] = (j < n) ? g_bkey[c * MAXPER + j] : 0ull;
    for (int j = lane; j < n; j += 32)
        sbox[j] = g_bbox[c * MAXPER + j];
    __syncwarp();

    // Bitonic sort descending over NP elements.
    for (int k = 2; k <= NP; k <<= 1) {
        for (int j = k >> 1; j > 0; j >>= 1) {
            for (int i = lane; i < NP; i += 32) {
                int l = i ^ j;
                if (l > i) {
                    bool up = ((i & k) == 0);   // ascending subsequence flag
                    unsigned long long a = skey[i], b = skey[l];
                    // descending sort: invert the ascending swap condition
                    if ((a < b) == up) { skey[i] = b; skey[l] = a; }
                }
            }
            __syncwarp();
        }
    }

    // Sorted scan.
    int m = 0;       // kept count
    int npick = 0;
    for (int i = 0; i < n && npick < MAXDET; i++) {
        unsigned long long key = skey[i];
        if (key == 0ull) break;               // padding (real keys nonzero)
        int slot = (int)(key & (MAXPER - 1));
        float4 b = sbox[slot];                // broadcast LDS
        float ab = (b.z - b.x) * (b.w - b.y);

        bool sup = false;
        for (int j0 = 0; j0 < m; j0 += 32) {
            bool p = false;
            int j = j0 + lane;
            if (j < m) {
                float4 kb = sbox[skept[j]];
                float iw = fminf(b.z, kb.z) - fmaxf(b.x, kb.x);
                float ih = fminf(b.w, kb.w) - fmaxf(b.y, kb.y);
                iw = fmaxf(iw, 0.0f);
                ih = fmaxf(ih, 0.0f);
                float inter = iw * ih;
                float uni = ab + (kb.z - kb.x) * (kb.w - kb.y) - inter;
                p = (inter / uni > IOU_THR);
            }
            if (__any_sync(0xffffffffu, p)) { sup = true; break; }
        }
        if (!sup) {
            if (lane == 0) {
                skept[m] = (unsigned short)slot;
                spick[npick] = key;
            }
            __syncwarp();
            m++;
            npick++;
        }
    }

    // Flush picks to the compact global list.
    int base = 0;
    if (lane == 0 && npick > 0) base = atomicAdd(&g_ptotal, npick);
    base = __shfl_sync(0xffffffffu, base, 0);
    for (int j = lane; j < npick; j += 32) {
        g_pkey[base + j] = spick[j];
        g_pcls[base + j] = c;
    }
}

// ---------------------------------------------------------------------------
// Select: exact global rank of every picked key by brute-force count over all
// picked keys (broadcast LDS sweep). rank < 300 -> scatter the output row.
// Keys are unique, so ranks are unique and rows land in merge order.
// ---------------------------------------------------------------------------
#define SEL_BLOCKS ((MAXPICK + 1023) / 1024)   // 24
#define SEL_SMEM   (MAXPICK * 8)               // 192000 B

extern __shared__ unsigned long long spk[];

__global__ __launch_bounds__(1024, 1) void select_kernel(float* __restrict__ out) {
    int P = g_ptotal;
    if (P > MAXPICK) P = MAXPICK;
    if (blockIdx.x * 1024 >= P) return;        // block-uniform early exit

    int tid = threadIdx.x;
    for (int j = tid; j < P; j += 1024) spk[j] = g_pkey[j];
    __syncthreads();

    int t = blockIdx.x * 1024 + tid;
    if (t >= P) return;

    unsigned long long mykey = spk[t];
    int cnt = 0;
    int j = 0;
    for (; j + 4 <= P; j += 4) {
        cnt += (spk[j]     > mykey);
        cnt += (spk[j + 1] > mykey);
        cnt += (spk[j + 2] > mykey);
        cnt += (spk[j + 3] > mykey);
    }
    for (; j < P; j++) cnt += (spk[j] > mykey);

    if (cnt < MAXDET) {
        int c    = g_pcls[t];
        int slot = (int)(mykey & (MAXPER - 1));
        float4 b = g_bbox[c * MAXPER + slot];
        float* row = out + cnt * 6;
        row[0] = b.x; row[1] = b.y; row[2] = b.z; row[3] = b.w;
        row[4] = __uint_as_float((unsigned int)(mykey >> 32));
        row[5] = (float)c;
    }
}

// ---------------------------------------------------------------------------
extern "C" void kernel_launch(void* const* d_in, const int* in_sizes, int n_in,
                              void* d_out, int out_size) {
    const float* pred = (const float*)d_in[0];
    const int*   oh   = (const int*)d_in[1];
    const int*   ow   = (const int*)d_in[2];
    float*       out  = (float*)d_out;

    cudaFuncSetAttribute(select_kernel,
                         cudaFuncAttributeMaxDynamicSharedMemorySize,
                         SEL_SMEM);

    init_kernel<<<8, 256>>>(out);
    int total_threads = NBOX * 32;  // one warp per box
    int blocks = (total_threads + 255) / 256;
    decode_kernel<<<blocks, 256>>>(pred, oh, ow);
    class_nms_kernel<<<NCLS, 32>>>();
    select_kernel<<<SEL_BLOCKS, 1024, SEL_SMEM>>>(out);
}

// round 5
// speedup vs baseline: 5.5440x; 5.5440x over previous
#include <cuda_runtime.h>

#define NBOX 10647
#define NCLS 80
#define MAXDET 300
#define SCORE_THR 0.3f
#define IOU_THR 0.45f
#define INPUT_SZ 416.0
#define MAXPER 1024              // per-class bucket capacity (expected ~93)
#define NMAX 256                 // matrix-path cap per class
#define WMAX (NMAX / 32)         // 8 words per suppression row
#define MAXPICK (NCLS * MAXDET)  // 24000
#define CCAP 2048                // candidate cap in select (expected ~310)

// Per-class buckets written by decode, read by class NMS.
__device__ float4             g_bbox[NCLS * MAXPER];
__device__ unsigned long long g_bkey[NCLS * MAXPER];
__device__ int                g_cnt[NCLS];

// Compact pick list written by class NMS, read by select.
__device__ unsigned long long g_pkey[MAXPICK];
__device__ unsigned char      g_pcls[MAXPICK];
__device__ int                g_ptotal;

// Decode constants (computed once in init).
__device__ float g_r, g_dw, g_dh, g_xmax, g_ymax;

// ---------------------------------------------------------------------------
// Init: zero output/counters; one thread hoists the FP64 resize math.
// ---------------------------------------------------------------------------
__global__ void init_kernel(float* __restrict__ out,
                            const int* __restrict__ p_oh,
                            const int* __restrict__ p_ow) {
    int t = blockIdx.x * blockDim.x + threadIdx.x;
    if (t < MAXDET * 6) out[t] = 0.0f;
    if (t < NCLS) g_cnt[t] = 0;
    if (t == NCLS) g_ptotal = 0;
    if (t == NCLS + 1) {
        int oh = p_oh[0], ow = p_ow[0];
        double rw = INPUT_SZ / (double)ow;
        double rh = INPUT_SZ / (double)oh;
        double rr = rw < rh ? rw : rh;
        g_r    = (float)rr;
        g_dw   = (float)((INPUT_SZ - rr * (double)ow) * 0.5);
        g_dh   = (float)((INPUT_SZ - rr * (double)oh) * 0.5);
        g_xmax = (float)(ow - 1);
        g_ymax = (float)(oh - 1);
    }
}

// ---------------------------------------------------------------------------
// Decode: one warp per box (pure fp32). Lanes argmax the 80 class probs
// (tie -> lowest class, matching jnp.argmax); lane 0 does box math and
// scatters survivors into per-class buckets.
// ---------------------------------------------------------------------------
__global__ void decode_kernel(const float* __restrict__ pred) {
    int gt   = blockIdx.x * blockDim.x + threadIdx.x;
    int box  = gt >> 5;
    int lane = gt & 31;
    if (box >= NBOX) return;

    const float* p = pred + box * 85;

    float best = -1.0f;
    int bestc = 0;
    for (int c = lane; c < NCLS; c += 32) {
        float v = p[5 + c];
        if (v > best) { best = v; bestc = c; }
    }
    for (int off = 16; off; off >>= 1) {
        float v2 = __shfl_xor_sync(0xffffffffu, best, off);
        int   c2 = __shfl_xor_sync(0xffffffffu, bestc, off);
        if (v2 > best || (v2 == best && c2 < bestc)) { best = v2; bestc = c2; }
    }
    if (lane) return;

    float r = g_r, dw = g_dw, dh = g_dh;
    float cx = p[0], cy = p[1], w = p[2], h = p[3], conf = p[4];
    float x1 = (cx - w * 0.5f - dw) / r;
    float y1 = (cy - h * 0.5f - dh) / r;
    float x2 = (cx + w * 0.5f - dw) / r;
    float y2 = (cy + h * 0.5f - dh) / r;
    x1 = fmaxf(x1, 0.0f);
    y1 = fmaxf(y1, 0.0f);
    x2 = fminf(x2, g_xmax);
    y2 = fminf(y2, g_ymax);
    if (x1 > x2 || y1 > y2) { x1 = y1 = x2 = y2 = 0.0f; }

    float area  = (x2 - x1) * (y2 - y1);
    float score = conf * best;
    if (!(area > 0.0f && score > SCORE_THR)) return;

    int slot = atomicAdd(&g_cnt[bestc], 1);
    if (slot < MAXPER) {
        g_bbox[bestc * MAXPER + slot] = make_float4(x1, y1, x2, y2);
        // key: score (desc) > orig index (asc via NBOX-box) > slot (10 bits).
        g_bkey[bestc * MAXPER + slot] =
            ((unsigned long long)__float_as_uint(score) << 32) |
            ((unsigned long long)(NBOX - box) << 10) |
            (unsigned long long)(slot & (MAXPER - 1));
    }
}

// ---------------------------------------------------------------------------
// Per-class NMS: one 128-thread block per class. Bitonic-sort keys desc,
// build the pairwise suppression bitmask matrix in parallel, then a short
// serial bitwise scan picks the kept boxes (== greedy NMS on sorted order,
// valid because suppression is strictly class-local).
// ---------------------------------------------------------------------------
__global__ __launch_bounds__(128, 1) void class_nms_kernel() {
    __shared__ unsigned long long skey[MAXPER];    // 8 KB
    __shared__ float4             sbox[MAXPER];    // 16 KB
    __shared__ unsigned int       srow[NMAX * WMAX]; // 8 KB (also u16 scratch)
    __shared__ unsigned long long spick[MAXDET];   // 2.4 KB
    __shared__ int s_npick, s_base;

    int c   = blockIdx.x;
    int tid = threadIdx.x;

    int n = g_cnt[c];
    if (n > MAXPER) n = MAXPER;
    if (n == 0) return;

    int NP = 1;
    while (NP < n) NP <<= 1;

    for (int j = tid; j < NP; j += 128)
        skey[j] = (j < n) ? g_bkey[c * MAXPER + j] : 0ull;
    for (int j = tid; j < n; j += 128)
        sbox[j] = g_bbox[c * MAXPER + j];
    __syncthreads();

    // Bitonic sort descending (validated in R4).
    for (int k = 2; k <= NP; k <<= 1) {
        for (int j = k >> 1; j > 0; j >>= 1) {
            for (int i = tid; i < NP; i += 128) {
                int l = i ^ j;
                if (l > i) {
                    bool up = ((i & k) == 0);
                    unsigned long long a = skey[i], b = skey[l];
                    if ((a < b) == up) { skey[i] = b; skey[l] = a; }
                }
            }
            __syncthreads();
        }
    }

    if (n <= NMAX) {
        // ---- parallel suppression-matrix build: bit j of row i = IoU(i,j)>thr, j<i ----
        int W = (n + 31) >> 5;
        for (int t = tid; t < n * W; t += 128) {
            int i = t / W, w = t % W;
            unsigned long long ki = skey[i];
            float4 bi = sbox[(int)(ki & (MAXPER - 1))];
            float ai = (bi.z - bi.x) * (bi.w - bi.y);
            unsigned int bits = 0;
            int jend = min(i, (w + 1) * 32);
            for (int j = w * 32; j < jend; j++) {
                float4 bj = sbox[(int)(skey[j] & (MAXPER - 1))];
                float iw = fminf(bi.z, bj.z) - fmaxf(bi.x, bj.x);
                float ih = fminf(bi.w, bj.w) - fmaxf(bi.y, bj.y);
                iw = fmaxf(iw, 0.0f);
                ih = fmaxf(ih, 0.0f);
                float inter = iw * ih;
                float uni = ai + (bj.z - bj.x) * (bj.w - bj.y) - inter;
                if (inter / uni > IOU_THR) bits |= 1u << (j & 31);
            }
            srow[i * W + w] = bits;
        }
        __syncthreads();
        // ---- serial bitwise scan (pure LOP, ~n iterations) ----
        if (tid == 0) {
            unsigned int kept[WMAX];
            #pragma unroll
            for (int w = 0; w < WMAX; w++) kept[w] = 0;
            int npick = 0;
            for (int i = 0; i < n && npick < MAXDET; i++) {
                unsigned int sup = 0;
                for (int w = 0; w < W; w++) sup |= srow[i * W + w] & kept[w];
                if (!sup) {
                    kept[i >> 5] |= 1u << (i & 31);
                    spick[npick++] = skey[i];
                }
            }
            s_npick = npick;
            s_base  = npick ? atomicAdd(&g_ptotal, npick) : 0;
        }
    } else {
        // ---- fallback (n > NMAX, statistically untaken): warp-0 sorted scan ----
        if (tid < 32) {
            int lane = tid;
            unsigned short* skept = (unsigned short*)srow;   // >= n entries
            int m = 0, npick = 0;
            for (int i = 0; i < n && npick < MAXDET; i++) {
                unsigned long long key = skey[i];
                float4 b = sbox[(int)(key & (MAXPER - 1))];
                float ab = (b.z - b.x) * (b.w - b.y);
                bool sup = false;
                for (int j0 = 0; j0 < m; j0 += 32) {
                    bool pr = false;
                    int j = j0 + lane;
                    if (j < m) {
                        float4 kb = sbox[skept[j]];
                        float iw = fminf(b.z, kb.z) - fmaxf(b.x, kb.x);
                        float ih = fminf(b.w, kb.w) - fmaxf(b.y, kb.y);
                        iw = fmaxf(iw, 0.0f);
                        ih = fmaxf(ih, 0.0f);
                        float inter = iw * ih;
                        float uni = ab + (kb.z - kb.x) * (kb.w - kb.y) - inter;
                        pr = (inter / uni > IOU_THR);
                    }
                    if (__any_sync(0xffffffffu, pr)) { sup = true; break; }
                }
                if (!sup) {
                    if (lane == 0) {
                        skept[m] = (unsigned short)(key & (MAXPER - 1));
                        spick[npick] = key;
                    }
                    __syncwarp();
                    m++; npick++;
                }
            }
            if (lane == 0) {
                s_npick = npick;
                s_base  = npick ? atomicAdd(&g_ptotal, npick) : 0;
            }
        }
    }
    __syncthreads();

    int npick = s_npick, base = s_base;
    for (int j = tid; j < npick; j += 128) {
        g_pkey[base + j] = spick[j];
        g_pcls[base + j] = (unsigned char)c;
    }
}

// ---------------------------------------------------------------------------
// Select: histogram score bits (monotone key prefix) -> threshold bin T such
// that bins>T hold <300 keys. Candidates = bins>=T (superset of top-300, and
// closed upward: any key greater than a candidate is a candidate), so rank
// within candidates == global rank. C ~ 310 => C^2 ranking is trivial.
// ---------------------------------------------------------------------------
__global__ __launch_bounds__(1024, 1) void select_kernel(float* __restrict__ out) {
    __shared__ unsigned int       hist[2048];   // 8 KB
    __shared__ unsigned int       super[64];
    __shared__ unsigned long long ckey[CCAP];   // 16 KB
    __shared__ unsigned char      ccls[CCAP];   // 2 KB
    __shared__ int s_T, s_C;

    int tid = threadIdx.x;
    int P = g_ptotal;
    if (P > MAXPICK) P = MAXPICK;

    for (int j = tid; j < 2048; j += 1024) hist[j] = 0;
    if (tid == 0) s_C = 0;
    __syncthreads();

    // scores in (0.3, 1]: bits in (0x3E99999A, 0x3F800000]; 2^13-wide bins.
    for (int j = tid; j < P; j += 1024) {
        unsigned int sb = (unsigned int)(g_pkey[j] >> 32);
        atomicAdd(&hist[(sb - 0x3E990000u) >> 13], 1u);
    }
    __syncthreads();
    if (tid < 64) {
        unsigned int s = 0;
        for (int w = 0; w < 32; w++) s += hist[tid * 32 + w];
        super[tid] = s;
    }
    __syncthreads();
    if (tid == 0) {
        int cum = 0, T = 0;
        int sb = 63;
        for (; sb >= 0; sb--) {
            if (cum + (int)super[sb] >= MAXDET) break;
            cum += (int)super[sb];
        }
        if (sb >= 0) {
            int b = sb * 32 + 31;
            for (; b >= sb * 32; b--) {
                cum += (int)hist[b];
                if (cum >= MAXDET) break;
            }
            T = (b < sb * 32) ? sb * 32 : b;
        }
        s_T = T;   // T==0 when P<300: everyone is a candidate
    }
    __syncthreads();

    int T = s_T;
    for (int j = tid; j < P; j += 1024) {
        unsigned long long k = g_pkey[j];
        int b = (int)(((unsigned int)(k >> 32) - 0x3E990000u) >> 13);
        if (b >= T) {
            int idx = atomicAdd(&s_C, 1);
            if (idx < CCAP) { ckey[idx] = k; ccls[idx] = g_pcls[j]; }
        }
    }
    __syncthreads();

    int C = s_C;
    if (C > CCAP) C = CCAP;
    for (int t = tid; t < C; t += 1024) {
        unsigned long long mk = ckey[t];
        int rank = 0;
        for (int j = 0; j < C; j++) rank += (ckey[j] > mk);
        if (rank < MAXDET) {
            int cls  = ccls[t];
            int slot = (int)(mk & (MAXPER - 1));
            float4 b = g_bbox[cls * MAXPER + slot];
            float* row = out + rank * 6;
            row[0] = b.x; row[1] = b.y; row[2] = b.z; row[3] = b.w;
            row[4] = __uint_as_float((unsigned int)(mk >> 32));
            row[5] = (float)cls;
        }
    }
}

// ---------------------------------------------------------------------------
extern "C" void kernel_launch(void* const* d_in, const int* in_sizes, int n_in,
                              void* d_out, int out_size) {
    const float* pred = (const float*)d_in[0];
    const int*   oh   = (const int*)d_in[1];
    const int*   ow   = (const int*)d_in[2];
    float*       out  = (float*)d_out;

    init_kernel<<<8, 256>>>(out, oh, ow);
    int total_threads = NBOX * 32;  // one warp per box
    int blocks = (total_threads + 255) / 256;
    decode_kernel<<<blocks, 256>>>(pred);
    class_nms_kernel<<<NCLS, 128>>>();
    select_kernel<<<1, 1024>>>(out);
}

// round 6
// speedup vs baseline: 7.2970x; 1.3162x over previous
#include <cuda_runtime.h>

#define NBOX 10647
#define NCLS 80
#define MAXDET 300
#define SCORE_THR 0.3f
#define IOU_THR 0.45f
#define INPUT_SZ 416.0
#define MAXPER 1024              // per-class bucket capacity (expected ~93)
#define NMAX 256                 // matrix-path cap per class
#define WMAX (NMAX / 32)
#define MAXPICK (NCLS * MAXDET)  // 24000
#define PCAP 12000               // smem key-cache capacity (expected ~6.5k)
#define CCAP 1024                // candidate cap (expected ~310)

// Per-class buckets written by decode, read by NMS.
__device__ float4             g_bbox[NCLS * MAXPER];
__device__ unsigned long long g_bkey[NCLS * MAXPER];
__device__ int                g_cnt[NCLS];        // zeroed by nms block c each run

// Compact pick list (nms phase -> select phase).
__device__ unsigned long long g_pkey[MAXPICK];
__device__ unsigned char      g_pcls[MAXPICK];
__device__ int                g_ptotal;           // reset by select phase
__device__ unsigned int       g_done;             // auto-wraps via atomicInc

// ---------------------------------------------------------------------------
// Decode: one warp per box (fp32; FP64 resize consts hoisted to once/block).
// Lanes argmax the 80 class probs (tie -> lowest class, matching jnp.argmax);
// lane 0 does box math and scatters survivors into per-class buckets.
// ---------------------------------------------------------------------------
__global__ void decode_kernel(const float* __restrict__ pred,
                              const int* __restrict__ p_oh,
                              const int* __restrict__ p_ow) {
    __shared__ float s_r, s_dw, s_dh, s_xmax, s_ymax;
    if (threadIdx.x == 0) {
        int oh = p_oh[0], ow = p_ow[0];
        double rw = INPUT_SZ / (double)ow;
        double rh = INPUT_SZ / (double)oh;
        double rr = rw < rh ? rw : rh;
        s_r    = (float)rr;
        s_dw   = (float)((INPUT_SZ - rr * (double)ow) * 0.5);
        s_dh   = (float)((INPUT_SZ - rr * (double)oh) * 0.5);
        s_xmax = (float)(ow - 1);
        s_ymax = (float)(oh - 1);
    }
    __syncthreads();

    int gt   = blockIdx.x * blockDim.x + threadIdx.x;
    int box  = gt >> 5;
    int lane = gt & 31;
    if (box >= NBOX) return;

    const float* p = pred + box * 85;

    float best = -1.0f;
    int bestc = 0;
    for (int c = lane; c < NCLS; c += 32) {
        float v = p[5 + c];
        if (v > best) { best = v; bestc = c; }
    }
    for (int off = 16; off; off >>= 1) {
        float v2 = __shfl_xor_sync(0xffffffffu, best, off);
        int   c2 = __shfl_xor_sync(0xffffffffu, bestc, off);
        if (v2 > best || (v2 == best && c2 < bestc)) { best = v2; bestc = c2; }
    }
    if (lane) return;

    float r = s_r, dw = s_dw, dh = s_dh;
    float cx = p[0], cy = p[1], w = p[2], h = p[3], conf = p[4];
    float x1 = (cx - w * 0.5f - dw) / r;
    float y1 = (cy - h * 0.5f - dh) / r;
    float x2 = (cx + w * 0.5f - dw) / r;
    float y2 = (cy + h * 0.5f - dh) / r;
    x1 = fmaxf(x1, 0.0f);
    y1 = fmaxf(y1, 0.0f);
    x2 = fminf(x2, s_xmax);
    y2 = fminf(y2, s_ymax);
    if (x1 > x2 || y1 > y2) { x1 = y1 = x2 = y2 = 0.0f; }

    float area  = (x2 - x1) * (y2 - y1);
    float score = conf * best;
    if (!(area > 0.0f && score > SCORE_THR)) return;

    int slot = atomicAdd(&g_cnt[bestc], 1);
    if (slot < MAXPER) {
        g_bbox[bestc * MAXPER + slot] = make_float4(x1, y1, x2, y2);
        // key: score (desc) > orig index (asc via NBOX-box) > slot (10 bits).
        g_bkey[bestc * MAXPER + slot] =
            ((unsigned long long)__float_as_uint(score) << 32) |
            ((unsigned long long)(NBOX - box) << 10) |
            (unsigned long long)(slot & (MAXPER - 1));
    }
}

// ---------------------------------------------------------------------------
// Fused per-class NMS + global select.
// Phase 1 (all 80 blocks): bitonic sort bucket desc, parallel suppression
//   bitmask matrix, short serial bitwise scan -> picks to global list.
// Phase 2 (last-arriving block, threadfence-reduction pattern): histogram
//   score bits -> top-300 threshold bin; candidates (upward-closed set) get
//   exact global rank by C^2 count; scatter rows. C ~ 310.
// ---------------------------------------------------------------------------
#define OFF_SBOX  (MAXPER * 8)
#define OFF_SROW  (OFF_SBOX + MAXPER * 16)
#define OFF_SPICK (OFF_SROW + NMAX * WMAX * 4)
#define DSMEM_P1  (OFF_SPICK + MAXDET * 8)
#define OFF_HIST  (PCAP * 8)
#define OFF_CKEY  (OFF_HIST + 2048 * 4)
#define OFF_CCLS  (OFF_CKEY + CCAP * 8)
#define DSMEM_P2  (OFF_CCLS + CCAP)
#define DSMEM_BYTES (DSMEM_P2 > DSMEM_P1 ? DSMEM_P2 : DSMEM_P1)

extern __shared__ unsigned char dsm[];

__global__ __launch_bounds__(512, 1) void nms_select_kernel(float* __restrict__ out) {
    unsigned long long* skey  = (unsigned long long*)dsm;
    float4*             sbox  = (float4*)(dsm + OFF_SBOX);
    unsigned int*       srow  = (unsigned int*)(dsm + OFF_SROW);
    unsigned long long* spick = (unsigned long long*)(dsm + OFF_SPICK);

    __shared__ int  s_npick, s_base;
    __shared__ bool amLast;

    int c   = blockIdx.x;
    int tid = threadIdx.x;

    int n = g_cnt[c];
    if (n > MAXPER) n = MAXPER;
    if (tid == 0) {
        g_cnt[c] = 0;                       // restore invariant for next replay
        s_npick = 0;
        s_base  = 0;
    }
    __syncthreads();

    if (n > 0) {
        int NP = 1;
        while (NP < n) NP <<= 1;

        for (int j = tid; j < NP; j += 512)
            skey[j] = (j < n) ? g_bkey[c * MAXPER + j] : 0ull;
        for (int j = tid; j < n; j += 512)
            sbox[j] = g_bbox[c * MAXPER + j];
        __syncthreads();

        // Bitonic sort descending.
        for (int k = 2; k <= NP; k <<= 1) {
            for (int j = k >> 1; j > 0; j >>= 1) {
                for (int i = tid; i < NP; i += 512) {
                    int l = i ^ j;
                    if (l > i) {
                        bool up = ((i & k) == 0);
                        unsigned long long a = skey[i], b = skey[l];
                        if ((a < b) == up) { skey[i] = b; skey[l] = a; }
                    }
                }
                __syncthreads();
            }
        }

        if (n <= NMAX) {
            // Parallel suppression matrix: bit j of row i = IoU(i,j)>thr, j<i.
            int W = (n + 31) >> 5;
            for (int t = tid; t < n * W; t += 512) {
                int i = t / W, w = t % W;
                float4 bi = sbox[(int)(skey[i] & (MAXPER - 1))];
                float ai = (bi.z - bi.x) * (bi.w - bi.y);
                unsigned int bits = 0;
                int jend = min(i, (w + 1) * 32);
                for (int j = w * 32; j < jend; j++) {
                    float4 bj = sbox[(int)(skey[j] & (MAXPER - 1))];
                    float iw = fminf(bi.z, bj.z) - fmaxf(bi.x, bj.x);
                    float ih = fminf(bi.w, bj.w) - fmaxf(bi.y, bj.y);
                    iw = fmaxf(iw, 0.0f);
                    ih = fmaxf(ih, 0.0f);
                    float inter = iw * ih;
                    float uni = ai + (bj.z - bj.x) * (bj.w - bj.y) - inter;
                    if (inter / uni > IOU_THR) bits |= 1u << (j & 31);
                }
                srow[i * W + w] = bits;
            }
            __syncthreads();
            // Serial bitwise scan (== greedy NMS on sorted order).
            if (tid == 0) {
                unsigned int kept[WMAX];
                #pragma unroll
                for (int w = 0; w < WMAX; w++) kept[w] = 0;
                int npick = 0;
                int W2 = W;
                for (int i = 0; i < n && npick < MAXDET; i++) {
                    unsigned int sup = 0;
                    for (int w = 0; w < W2; w++) sup |= srow[i * W2 + w] & kept[w];
                    if (!sup) {
                        kept[i >> 5] |= 1u << (i & 31);
                        spick[npick++] = skey[i];
                    }
                }
                s_npick = npick;
                s_base  = npick ? atomicAdd(&g_ptotal, npick) : 0;
            }
        } else {
            // Fallback (n > NMAX, statistically untaken): warp-0 sorted scan.
            if (tid < 32) {
                int lane = tid;
                unsigned short* skept = (unsigned short*)srow;
                int m = 0, npick = 0;
                for (int i = 0; i < n && npick < MAXDET; i++) {
                    unsigned long long key = skey[i];
                    float4 b = sbox[(int)(key & (MAXPER - 1))];
                    float ab = (b.z - b.x) * (b.w - b.y);
                    bool sup = false;
                    for (int j0 = 0; j0 < m; j0 += 32) {
                        bool pr = false;
                        int j = j0 + lane;
                        if (j < m) {
                            float4 kb = sbox[skept[j]];
                            float iw = fminf(b.z, kb.z) - fmaxf(b.x, kb.x);
                            float ih = fminf(b.w, kb.w) - fmaxf(b.y, kb.y);
                            iw = fmaxf(iw, 0.0f);
                            ih = fmaxf(ih, 0.0f);
                            float inter = iw * ih;
                            float uni = ab + (kb.z - kb.x) * (kb.w - kb.y) - inter;
                            pr = (inter / uni > IOU_THR);
                        }
                        if (__any_sync(0xffffffffu, pr)) { sup = true; break; }
                    }
                    if (!sup) {
                        if (lane == 0) {
                            skept[m] = (unsigned short)(key & (MAXPER - 1));
                            spick[npick] = key;
                        }
                        __syncwarp();
                        m++; npick++;
                    }
                }
                if (lane == 0) {
                    s_npick = npick;
                    s_base  = npick ? atomicAdd(&g_ptotal, npick) : 0;
                }
            }
        }
        __syncthreads();

        int npick = s_npick, base = s_base;
        for (int j = tid; j < npick; j += 512) {
            g_pkey[base + j] = spick[j];
            g_pcls[base + j] = (unsigned char)c;
        }
    }

    // ---- threadfence-reduction handoff: last block runs select ----
    __threadfence();
    if (tid == 0)
        amLast = (atomicInc(&g_done, NCLS - 1) == NCLS - 1);  // auto-resets
    __syncthreads();
    if (!amLast) return;

    unsigned long long* pk   = (unsigned long long*)dsm;
    unsigned int*       hist = (unsigned int*)(dsm + OFF_HIST);
    unsigned long long* ckey = (unsigned long long*)(dsm + OFF_CKEY);
    unsigned char*      ccls = (unsigned char*)(dsm + OFF_CCLS);
    __shared__ unsigned int super[64];
    __shared__ int s_T, s_C, s_P;

    if (tid == 0) {
        s_P = g_ptotal;
        g_ptotal = 0;                       // restore invariant
        s_C = 0;
    }
    for (int j = tid; j < MAXDET * 6; j += 512) out[j] = 0.0f;
    for (int j = tid; j < 2048; j += 512) hist[j] = 0;
    __syncthreads();

    int P = s_P;
    if (P > MAXPICK) P = MAXPICK;
    bool cached = (P <= PCAP);

    // Single sweep: cache keys in smem + histogram score bits.
    // scores in (0.3, 1]: bits - 0x3E990000 >> 13 lands in [0, 1848) < 2048.
    for (int j = tid; j < P; j += 512) {
        unsigned long long k = g_pkey[j];
        if (cached) pk[j] = k;
        atomicAdd(&hist[((unsigned int)(k >> 32) - 0x3E990000u) >> 13], 1u);
    }
    __syncthreads();
    if (tid < 64) {
        unsigned int s = 0;
        for (int w = 0; w < 32; w++) s += hist[tid * 32 + w];
        super[tid] = s;
    }
    __syncthreads();
    if (tid == 0) {
        int cum = 0, T = 0;
        int sb = 63;
        for (; sb >= 0; sb--) {
            if (cum + (int)super[sb] >= MAXDET) break;
            cum += (int)super[sb];
        }
        if (sb >= 0) {
            int b = sb * 32 + 31;
            for (; b >= sb * 32; b--) {
                cum += (int)hist[b];
                if (cum >= MAXDET) break;
            }
            T = (b < sb * 32) ? sb * 32 : b;
        }
        s_T = T;                            // T==0 when P<300: all candidates
    }
    __syncthreads();

    int T = s_T;
    for (int j = tid; j < P; j += 512) {
        unsigned long long k = cached ? pk[j] : g_pkey[j];
        int b = (int)(((unsigned int)(k >> 32) - 0x3E990000u) >> 13);
        if (b >= T) {
            int idx = atomicAdd(&s_C, 1);
            if (idx < CCAP) { ckey[idx] = k; ccls[idx] = g_pcls[j]; }
        }
    }
    __syncthreads();

    int C = s_C;
    if (C > CCAP) C = CCAP;
    for (int t = tid; t < C; t += 512) {
        unsigned long long mk = ckey[t];
        int rank = 0;
        for (int j = 0; j < C; j++) rank += (ckey[j] > mk);
        if (rank < MAXDET) {
            int cls  = ccls[t];
            int slot = (int)(mk & (MAXPER - 1));
            float4 b = g_bbox[cls * MAXPER + slot];
            float* row = out + rank * 6;
            row[0] = b.x; row[1] = b.y; row[2] = b.z; row[3] = b.w;
            row[4] = __uint_as_float((unsigned int)(mk >> 32));
            row[5] = (float)cls;
        }
    }
}

// ---------------------------------------------------------------------------
extern "C" void kernel_launch(void* const* d_in, const int* in_sizes, int n_in,
                              void* d_out, int out_size) {
    const float* pred = (const float*)d_in[0];
    const int*   oh   = (const int*)d_in[1];
    const int*   ow   = (const int*)d_in[2];
    float*       out  = (float*)d_out;

    cudaFuncSetAttribute(nms_select_kernel,
                         cudaFuncAttributeMaxDynamicSharedMemorySize,
                         DSMEM_BYTES);

    int total_threads = NBOX * 32;  // one warp per box
    int blocks = (total_threads + 255) / 256;
    decode_kernel<<<blocks, 256>>>(pred, oh, ow);
    nms_select_kernel<<<NCLS, 512, DSMEM_BYTES>>>(out);
}